// round 17
// baseline (speedup 1.0000x reference)
#include <cuda_runtime.h>
#include <cstdint>

// out[i, :] = weight[b[i], :], out[0, :] = 0.   N=1e6 cells, 32 f32 each.
//
// R17: all store-path variants (STG.128/STG.256/TMA/phase-sep) land at
// 21.5-23us with no pipe >60% -> L2 write+evict path ceiling (output is
// partially dirty-resident in 126MB L2 across replays; write 128MB + evict
// ~72MB through LTS). Last lever: remove wave quantization (26.4 waves,
// 40% tail) with a persistent grid-stride loop, 1184 CTAs x ~3.3 tiles.
// Body identical to proven R14: STG.256, U=4 batched idx loads.

constexpr int BLOCK = 256;
constexpr int U = 4;

__device__ __forceinline__ void ldg256(const float* p, unsigned r[8]) {
    asm volatile("ld.global.nc.v8.b32 {%0,%1,%2,%3,%4,%5,%6,%7}, [%8];"
                 : "=r"(r[0]), "=r"(r[1]), "=r"(r[2]), "=r"(r[3]),
                   "=r"(r[4]), "=r"(r[5]), "=r"(r[6]), "=r"(r[7])
                 : "l"(p));
}

__device__ __forceinline__ void stg256(float* p, const unsigned r[8]) {
    asm volatile("st.global.v8.b32 [%0], {%1,%2,%3,%4,%5,%6,%7,%8};"
                 :: "l"(p),
                    "r"(r[0]), "r"(r[1]), "r"(r[2]), "r"(r[3]),
                    "r"(r[4]), "r"(r[5]), "r"(r[6]), "r"(r[7])
                 : "memory");
}

__global__ __launch_bounds__(BLOCK)
void batch_effect_kernel(const int* __restrict__ b,
                         const float* __restrict__ w,
                         float* __restrict__ out,
                         unsigned int total32)   // 32B chunks = N*4
{
    const unsigned int tile_sz = BLOCK * U;                 // 1024 chunks
    const unsigned int stride = gridDim.x * tile_sz;

    for (unsigned int base = blockIdx.x * tile_sz; base < total32;
         base += stride) {

        unsigned int c0 = base + threadIdx.x;

        if (base + tile_sz <= total32) {
            // Full tile: batch the 4 index loads (MLP), then gather+store.
            int bi[U];
            #pragma unroll
            for (int u = 0; u < U; u++) {
                unsigned int c = c0 + u * BLOCK;
                bi[u] = __ldg(&b[c >> 2]);      // cell = c/4
            }
            #pragma unroll
            for (int u = 0; u < U; u++) {
                unsigned int c = c0 + u * BLOCK;
                unsigned r[8];
                ldg256(w + ((unsigned)bi[u] << 5) + ((c & 3u) << 3), r);
                if (c < 4u) {
                    #pragma unroll
                    for (int k = 0; k < 8; k++) r[k] = 0u;
                }
                stg256(out + (c << 3), r);
            }
        } else {
            // Tail tile
            #pragma unroll
            for (int u = 0; u < U; u++) {
                unsigned int c = c0 + u * BLOCK;
                if (c < total32) {
                    int bi = __ldg(&b[c >> 2]);
                    unsigned r[8];
                    ldg256(w + ((unsigned)bi << 5) + ((c & 3u) << 3), r);
                    if (c < 4u) {
                        #pragma unroll
                        for (int k = 0; k < 8; k++) r[k] = 0u;
                    }
                    stg256(out + (c << 3), r);
                }
            }
        }
    }
}

extern "C" void kernel_launch(void* const* d_in, const int* in_sizes, int n_in,
                              void* d_out, int out_size)
{
    const int* b = (const int*)d_in[0];          // [N, 1] int32
    const float* w = (const float*)d_in[1];      // [64, 32] f32
    float* out = (float*)d_out;                  // [N, 32] f32

    unsigned int n_cells = (unsigned int)in_sizes[0];
    unsigned int total32 = n_cells * 4u;         // 4e6
    unsigned int tile_sz = BLOCK * U;            // 1024 chunks per CTA-tile

    unsigned int n_tiles = (total32 + tile_sz - 1) / tile_sz;
    unsigned int grid = 148u * 8u;               // persistent-ish, 8 CTAs/SM
    if (grid > n_tiles) grid = n_tiles;

    batch_effect_kernel<<<grid, BLOCK>>>(b, w, out, total32);
}